// round 2
// baseline (speedup 1.0000x reference)
#include <cuda_runtime.h>
#include <cuda_bf16.h>

// Problem constants (from reference): B=1024, T=1024, D=2, H=32, L=3.
// Key algebraic facts exploited:
//  * Only x[b, T-1, :] contributes to the output (last timestep only).
//  * hx == 0 for every cell  ->  Wh* are dead, biases combine to bx+bh.
//  * cx == 0 for layer 0     ->  layer-0 forget gate is dead.
// So the whole model is 1024 independent tiny MLP-ish evaluations.

#define BB 1024
#define TT 1024
#define DD 2
#define HH 32
#define GG 128  // 4*H

#define THREADS 1024
#define WARPS_PER_BLOCK (THREADS / 32)
#define NBLOCKS (BB / WARPS_PER_BLOCK)  // 32

__device__ __forceinline__ float sigmoid_f(float v) {
    return 1.0f / (1.0f + __expf(-v));
}

__global__ __launch_bounds__(THREADS)
void lstm_last_step_kernel(
    const float* __restrict__ x,
    const float* __restrict__ Wx0, const float* __restrict__ bx0, const float* __restrict__ bh0,
    const float* __restrict__ Wx1, const float* __restrict__ bx1, const float* __restrict__ bh1,
    const float* __restrict__ Wx2, const float* __restrict__ bx2, const float* __restrict__ bh2,
    const float* __restrict__ Wfc, const float* __restrict__ bfc,
    float* __restrict__ out)
{
    // Staged weights. W1/W2 transposed: sW?T[m][k] = Wx?[k][m] so that the
    // inner-product loop reads are consecutive across lanes (conflict-free).
    __shared__ float sW0[GG * DD];     // layer0 weights, row-major [128][2]
    __shared__ float sb0[GG];
    __shared__ float sW1T[HH][GG];     // 16 KB
    __shared__ float sb1[GG];
    __shared__ float sW2T[HH][GG];     // 16 KB
    __shared__ float sb2[GG];
    __shared__ float sWfc[HH];
    __shared__ float sbfc;

    const int tid = threadIdx.x;

    if (tid < GG * DD) sW0[tid] = Wx0[tid];
    if (tid >= GG * DD && tid < GG * DD + GG) {
        const int i = tid - GG * DD;
        sb0[i] = bx0[i] + bh0[i];
        sb1[i] = bx1[i] + bh1[i];
        sb2[i] = bx2[i] + bh2[i];
    }
    for (int i = tid; i < GG * HH; i += THREADS) {
        const int k = i >> 5;          // gate row 0..127
        const int m = i & 31;          // input dim 0..31
        sW1T[m][k] = Wx1[i];
        sW2T[m][k] = Wx2[i];
    }
    if (tid >= 512 && tid < 512 + HH) sWfc[tid - 512] = Wfc[tid - 512];
    if (tid == 600) sbfc = bfc[0];
    __syncthreads();

    const int warp = tid >> 5;
    const int lane = tid & 31;
    const int b = blockIdx.x * WARPS_PER_BLOCK + warp;   // one warp per batch row

    // x[b, T-1, 0..1]  (D=2 -> one float2)
    const float2 xv = *(const float2*)(x + (size_t)b * TT * DD + (size_t)(TT - 1) * DD);
    const float x0 = xv.x, x1 = xv.y;

    const int kI = lane;
    const int kF = 32 + lane;
    const int kG = 64 + lane;
    const int kO = 96 + lane;

    // ---- layer 0 (cx = 0 -> forget gate dead) ----
    float gI = fmaf(sW0[2 * kI], x0, fmaf(sW0[2 * kI + 1], x1, sb0[kI]));
    float gG = fmaf(sW0[2 * kG], x0, fmaf(sW0[2 * kG + 1], x1, sb0[kG]));
    float gO = fmaf(sW0[2 * kO], x0, fmaf(sW0[2 * kO + 1], x1, sb0[kO]));

    float c = sigmoid_f(gI) * tanhf(gG);
    float h = sigmoid_f(gO) * tanhf(c);

    // ---- layer 1 ----
    {
        float aI = sb1[kI], aF = sb1[kF], aG = sb1[kG], aO = sb1[kO];
        #pragma unroll
        for (int m = 0; m < HH; m++) {
            const float hm = __shfl_sync(0xffffffffu, h, m);
            aI = fmaf(sW1T[m][kI], hm, aI);
            aF = fmaf(sW1T[m][kF], hm, aF);
            aG = fmaf(sW1T[m][kG], hm, aG);
            aO = fmaf(sW1T[m][kO], hm, aO);
        }
        c = fmaf(c, sigmoid_f(aF), sigmoid_f(aI) * tanhf(aG));
        h = sigmoid_f(aO) * tanhf(c);
    }

    // ---- layer 2 ----
    {
        float aI = sb2[kI], aF = sb2[kF], aG = sb2[kG], aO = sb2[kO];
        #pragma unroll
        for (int m = 0; m < HH; m++) {
            const float hm = __shfl_sync(0xffffffffu, h, m);
            aI = fmaf(sW2T[m][kI], hm, aI);
            aF = fmaf(sW2T[m][kF], hm, aF);
            aG = fmaf(sW2T[m][kG], hm, aG);
            aO = fmaf(sW2T[m][kO], hm, aO);
        }
        c = fmaf(c, sigmoid_f(aF), sigmoid_f(aI) * tanhf(aG));
        h = sigmoid_f(aO) * tanhf(c);
    }

    // ---- fc: out[b] = sum_j h[j] * Wfc[j] + bfc ----
    float p = h * sWfc[lane];
    #pragma unroll
    for (int off = 16; off; off >>= 1)
        p += __shfl_xor_sync(0xffffffffu, p, off);

    if (lane == 0) out[b] = p + sbfc;
}

extern "C" void kernel_launch(void* const* d_in, const int* in_sizes, int n_in,
                              void* d_out, int out_size) {
    // metadata order:
    // 0:x 1:Wx0 2:bx0 3:Wh0 4:bh0 5:Wx1 6:bx1 7:Wh1 8:bh1
    // 9:Wx2 10:bx2 11:Wh2 12:bh2 13:Wfc 14:bfc
    const float* x   = (const float*)d_in[0];
    const float* Wx0 = (const float*)d_in[1];
    const float* bx0 = (const float*)d_in[2];
    const float* bh0 = (const float*)d_in[4];
    const float* Wx1 = (const float*)d_in[5];
    const float* bx1 = (const float*)d_in[6];
    const float* bh1 = (const float*)d_in[8];
    const float* Wx2 = (const float*)d_in[9];
    const float* bx2 = (const float*)d_in[10];
    const float* bh2 = (const float*)d_in[12];
    const float* Wfc = (const float*)d_in[13];
    const float* bfc = (const float*)d_in[14];
    float* out = (float*)d_out;

    lstm_last_step_kernel<<<NBLOCKS, THREADS>>>(
        x, Wx0, bx0, bh0, Wx1, bx1, bh1, Wx2, bx2, bh2, Wfc, bfc, out);
}

// round 4
// speedup vs baseline: 1.8294x; 1.8294x over previous
#include <cuda_runtime.h>
#include <cuda_bf16.h>

// B=1024, T=1024, D=2, H=32, L=3.
// Algebra: only x[b,T-1,:] matters; hx==0 -> Wh dead, biases fold;
// cx==0 in layer 0 -> its forget gate dead.
//
// Changes vs R2 baseline (evidence: issue=33.8% on 32 SMs, ~1060 instr/warp):
//  * padded natural weight layout [128][36]: conflict-free STS (staging was
//    32-way conflicted) and conflict-free LDS.128 in the mainloop (4x fewer LDS)
//  * __expf-based tanh/sigmoid instead of library tanhf (~40 instr -> ~3)
//  * 64 blocks x 512 threads: 2x SMs, 4 warps/SMSP

#define BB 1024
#define TT 1024
#define DD 2
#define HH 32
#define GG 128           // 4*H
#define WPAD 36          // row pitch (floats): 16B-multiple, bank-spreading
#define THREADS 512
#define WARPS 16
#define NBLOCKS (BB / WARPS)   // 64

__device__ __forceinline__ float fast_sigmoid(float v) {
    return __fdividef(1.0f, 1.0f + __expf(-v));
}
__device__ __forceinline__ float fast_tanh(float v) {
    return 1.0f - __fdividef(2.0f, 1.0f + __expf(2.0f * v));
}

__global__ __launch_bounds__(THREADS)
void lstm_last_step_kernel(
    const float* __restrict__ x,
    const float* __restrict__ Wx0, const float* __restrict__ bx0, const float* __restrict__ bh0,
    const float* __restrict__ Wx1, const float* __restrict__ bx1, const float* __restrict__ bh1,
    const float* __restrict__ Wx2, const float* __restrict__ bx2, const float* __restrict__ bh2,
    const float* __restrict__ Wfc, const float* __restrict__ bfc,
    float* __restrict__ out)
{
    __shared__ float sW0[GG * DD];        // [128][2] row-major
    __shared__ float sb0[GG];
    __shared__ float sW1[GG * WPAD];      // [128][36] padded row-major, 18 KB
    __shared__ float sb1[GG];
    __shared__ float sW2[GG * WPAD];      // 18 KB
    __shared__ float sb2[GG];
    __shared__ float sWfc[HH];
    __shared__ float sbfc;

    const int tid = threadIdx.x;

    if (tid < GG * DD) sW0[tid] = Wx0[tid];
    if (tid < GG) {
        sb0[tid] = bx0[tid] + bh0[tid];
        sb1[tid] = bx1[tid] + bh1[tid];
        sb2[tid] = bx2[tid] + bh2[tid];
    }
    // Natural layout: i = k*32 + m -> sW[k*36 + m]. Within a warp m = lane
    // varies -> consecutive banks -> conflict-free STS; LDG fully coalesced.
    #pragma unroll
    for (int i = tid; i < GG * HH; i += THREADS) {
        const int k = i >> 5;
        const int m = i & 31;
        sW1[k * WPAD + m] = Wx1[i];
        sW2[k * WPAD + m] = Wx2[i];
    }
    if (tid >= 256 && tid < 256 + HH) sWfc[tid - 256] = Wfc[tid - 256];
    if (tid == 300) sbfc = bfc[0];
    __syncthreads();

    const int warp = tid >> 5;
    const int lane = tid & 31;
    const int b = blockIdx.x * WARPS + warp;   // one warp per batch row

    // x[b, T-1, :]
    const float2 xv = *(const float2*)(x + (size_t)b * TT * DD + (size_t)(TT - 1) * DD);
    const float x0 = xv.x, x1 = xv.y;

    const int kI = lane;
    const int kF = 32 + lane;
    const int kG = 64 + lane;
    const int kO = 96 + lane;

    // ---- layer 0 (cx = 0 -> forget gate dead) ----
    float gI = fmaf(sW0[2 * kI], x0, fmaf(sW0[2 * kI + 1], x1, sb0[kI]));
    float gG = fmaf(sW0[2 * kG], x0, fmaf(sW0[2 * kG + 1], x1, sb0[kG]));
    float gO = fmaf(sW0[2 * kO], x0, fmaf(sW0[2 * kO + 1], x1, sb0[kO]));

    float c = fast_sigmoid(gI) * fast_tanh(gG);
    float h = fast_sigmoid(gO) * fast_tanh(c);

    // ---- layers 1 and 2: gates = W @ h + b, h broadcast via shfl ----
    #pragma unroll
    for (int layer = 0; layer < 2; layer++) {
        const float* sW = (layer == 0) ? sW1 : sW2;
        const float* sb = (layer == 0) ? sb1 : sb2;

        // Per-lane row base pointers; row pitch 144B keeps float4 alignment
        // and gives conflict-free 128-bit LDS (banks 4l..4l+3 per phase).
        const float4* rI = (const float4*)(sW + kI * WPAD);
        const float4* rF = (const float4*)(sW + kF * WPAD);
        const float4* rG = (const float4*)(sW + kG * WPAD);
        const float4* rO = (const float4*)(sW + kO * WPAD);

        float aI = sb[kI], aF = sb[kF], aG = sb[kG], aO = sb[kO];

        #pragma unroll
        for (int q = 0; q < HH / 4; q++) {
            const float h0 = __shfl_sync(0xffffffffu, h, 4 * q + 0);
            const float h1 = __shfl_sync(0xffffffffu, h, 4 * q + 1);
            const float h2 = __shfl_sync(0xffffffffu, h, 4 * q + 2);
            const float h3 = __shfl_sync(0xffffffffu, h, 4 * q + 3);
            const float4 wI = rI[q];
            const float4 wF = rF[q];
            const float4 wG = rG[q];
            const float4 wO = rO[q];
            aI = fmaf(wI.x, h0, fmaf(wI.y, h1, fmaf(wI.z, h2, fmaf(wI.w, h3, aI))));
            aF = fmaf(wF.x, h0, fmaf(wF.y, h1, fmaf(wF.z, h2, fmaf(wF.w, h3, aF))));
            aG = fmaf(wG.x, h0, fmaf(wG.y, h1, fmaf(wG.z, h2, fmaf(wG.w, h3, aG))));
            aO = fmaf(wO.x, h0, fmaf(wO.y, h1, fmaf(wO.z, h2, fmaf(wO.w, h3, aO))));
        }

        c = fmaf(c, fast_sigmoid(aF), fast_sigmoid(aI) * fast_tanh(aG));
        h = fast_sigmoid(aO) * fast_tanh(c);
    }

    // ---- fc: out[b] = sum_j h[j] * Wfc[j] + bfc ----
    float p = h * sWfc[lane];
    #pragma unroll
    for (int off = 16; off; off >>= 1)
        p += __shfl_xor_sync(0xffffffffu, p, off);

    if (lane == 0) out[b] = p + sbfc;
}

extern "C" void kernel_launch(void* const* d_in, const int* in_sizes, int n_in,
                              void* d_out, int out_size) {
    // 0:x 1:Wx0 2:bx0 3:Wh0 4:bh0 5:Wx1 6:bx1 7:Wh1 8:bh1
    // 9:Wx2 10:bx2 11:Wh2 12:bh2 13:Wfc 14:bfc
    const float* x   = (const float*)d_in[0];
    const float* Wx0 = (const float*)d_in[1];
    const float* bx0 = (const float*)d_in[2];
    const float* bh0 = (const float*)d_in[4];
    const float* Wx1 = (const float*)d_in[5];
    const float* bx1 = (const float*)d_in[6];
    const float* bh1 = (const float*)d_in[8];
    const float* Wx2 = (const float*)d_in[9];
    const float* bx2 = (const float*)d_in[10];
    const float* bh2 = (const float*)d_in[12];
    const float* Wfc = (const float*)d_in[13];
    const float* bfc = (const float*)d_in[14];
    float* out = (float*)d_out;

    lstm_last_step_kernel<<<NBLOCKS, THREADS>>>(
        x, Wx0, bx0, bh0, Wx1, bx1, bh1, Wx2, bx2, bh2, Wfc, bfc, out);
}

// round 5
// speedup vs baseline: 2.0150x; 1.1015x over previous
#include <cuda_runtime.h>
#include <cuda_bf16.h>

// B=1024, T=1024, D=2, H=32, L=3.
// Algebra: only x[b,T-1,:] matters; hx==0 -> Wh dead, biases fold;
// cx==0 in layer 0 -> its forget gate dead.
//
// R5 changes vs R4 (evidence: issue=26%, occ=24.5%, all pipes idle ->
// latency/overhead bound, serialized stage->bar->compute on 64 SMs):
//  * 128 blocks x 256 threads -> 128 SMs, half the per-SM compute
//  * layer-0 weights + Wfc/bfc read directly from L2 (no smem, no barrier
//    dependency) -> layer-0 compute overlaps W1/W2 staging latency
//  * W1/W2 staged via float4 LDG/STS (4+4 per thread, was 16+16 scalar)

#define BB 1024
#define TT 1024
#define DD 2
#define HH 32
#define GG 128           // 4*H
#define WPAD 36          // row pitch in floats: 16B multiple, bank-spreading
#define THREADS 256
#define WARPS 8
#define NBLOCKS (BB / WARPS)   // 128

__device__ __forceinline__ float fast_sigmoid(float v) {
    return __fdividef(1.0f, 1.0f + __expf(-v));
}
__device__ __forceinline__ float fast_tanh(float v) {
    return 1.0f - __fdividef(2.0f, 1.0f + __expf(2.0f * v));
}

__global__ __launch_bounds__(THREADS)
void lstm_last_step_kernel(
    const float* __restrict__ x,
    const float* __restrict__ Wx0, const float* __restrict__ bx0, const float* __restrict__ bh0,
    const float* __restrict__ Wx1, const float* __restrict__ bx1, const float* __restrict__ bh1,
    const float* __restrict__ Wx2, const float* __restrict__ bx2, const float* __restrict__ bh2,
    const float* __restrict__ Wfc, const float* __restrict__ bfc,
    float* __restrict__ out)
{
    __shared__ float sW1[GG * WPAD];      // [128][36] padded row-major, 18 KB
    __shared__ float sW2[GG * WPAD];      // 18 KB
    __shared__ float sb1[GG];
    __shared__ float sb2[GG];

    const int tid  = threadIdx.x;
    const int warp = tid >> 5;
    const int lane = tid & 31;
    const int b = blockIdx.x * WARPS + warp;   // one warp per batch row

    // ---- kick off W1/W2 staging loads early (float4, coalesced) ----
    const float4* W1v = (const float4*)Wx1;   // 1024 float4 total
    const float4* W2v = (const float4*)Wx2;
    float4 r1[4], r2[4];
    #pragma unroll
    for (int j = 0; j < 4; j++) {
        r1[j] = W1v[tid + 256 * j];
        r2[j] = W2v[tid + 256 * j];
    }
    float bias1 = 0.f, bias2 = 0.f;
    if (tid < GG) {
        bias1 = bx1[tid] + bh1[tid];
        bias2 = bx2[tid] + bh2[tid];
    }

    // ---- layer 0 directly from global (overlaps staging latency) ----
    const int kI = lane;
    const int kG = 64 + lane;
    const int kO = 96 + lane;

    const float2 xv = *(const float2*)(x + (size_t)b * TT * DD + (size_t)(TT - 1) * DD);
    const float2* W0v = (const float2*)Wx0;            // row k -> one float2
    const float2 wI0 = W0v[kI];
    const float2 wG0 = W0v[kG];
    const float2 wO0 = W0v[kO];
    const float b0I = bx0[kI] + bh0[kI];
    const float b0G = bx0[kG] + bh0[kG];
    const float b0O = bx0[kO] + bh0[kO];
    const float wfc = Wfc[lane];
    const float bfcv = bfc[0];

    // ---- store staged W1/W2 into padded smem ----
    #pragma unroll
    for (int j = 0; j < 4; j++) {
        const int i = tid + 256 * j;       // float4 index 0..1023
        const int k = i >> 3;              // gate row 0..127 (8 float4/row)
        const int q = i & 7;               // float4 within row
        ((float4*)(sW1 + k * WPAD))[q] = r1[j];
        ((float4*)(sW2 + k * WPAD))[q] = r2[j];
    }
    if (tid < GG) { sb1[tid] = bias1; sb2[tid] = bias2; }

    // layer-0 compute while other warps finish staging stores
    float gI = fmaf(wI0.x, xv.x, fmaf(wI0.y, xv.y, b0I));
    float gG = fmaf(wG0.x, xv.x, fmaf(wG0.y, xv.y, b0G));
    float gO = fmaf(wO0.x, xv.x, fmaf(wO0.y, xv.y, b0O));

    float c = fast_sigmoid(gI) * fast_tanh(gG);
    float h = fast_sigmoid(gO) * fast_tanh(c);

    __syncthreads();

    // ---- layers 1 and 2: gates = W @ h + b, h broadcast via shfl ----
    const int kF = 32 + lane;
    #pragma unroll
    for (int layer = 0; layer < 2; layer++) {
        const float* sW = (layer == 0) ? sW1 : sW2;
        const float* sb = (layer == 0) ? sb1 : sb2;

        // Row pitch 144B: float4-aligned, conflict-free LDS.128.
        const float4* rI = (const float4*)(sW + kI * WPAD);
        const float4* rF = (const float4*)(sW + kF * WPAD);
        const float4* rG = (const float4*)(sW + kG * WPAD);
        const float4* rO = (const float4*)(sW + kO * WPAD);

        float aI = sb[kI], aF = sb[kF], aG = sb[kG], aO = sb[kO];

        #pragma unroll
        for (int q = 0; q < HH / 4; q++) {
            const float h0 = __shfl_sync(0xffffffffu, h, 4 * q + 0);
            const float h1 = __shfl_sync(0xffffffffu, h, 4 * q + 1);
            const float h2 = __shfl_sync(0xffffffffu, h, 4 * q + 2);
            const float h3 = __shfl_sync(0xffffffffu, h, 4 * q + 3);
            const float4 wI = rI[q];
            const float4 wF = rF[q];
            const float4 wG = rG[q];
            const float4 wO = rO[q];
            aI = fmaf(wI.x, h0, fmaf(wI.y, h1, fmaf(wI.z, h2, fmaf(wI.w, h3, aI))));
            aF = fmaf(wF.x, h0, fmaf(wF.y, h1, fmaf(wF.z, h2, fmaf(wF.w, h3, aF))));
            aG = fmaf(wG.x, h0, fmaf(wG.y, h1, fmaf(wG.z, h2, fmaf(wG.w, h3, aG))));
            aO = fmaf(wO.x, h0, fmaf(wO.y, h1, fmaf(wO.z, h2, fmaf(wO.w, h3, aO))));
        }

        c = fmaf(c, fast_sigmoid(aF), fast_sigmoid(aI) * fast_tanh(aG));
        h = fast_sigmoid(aO) * fast_tanh(c);
    }

    // ---- fc: out[b] = sum_j h[j] * Wfc[j] + bfc ----
    float p = h * wfc;
    #pragma unroll
    for (int off = 16; off; off >>= 1)
        p += __shfl_xor_sync(0xffffffffu, p, off);

    if (lane == 0) out[b] = p + bfcv;
}

extern "C" void kernel_launch(void* const* d_in, const int* in_sizes, int n_in,
                              void* d_out, int out_size) {
    // 0:x 1:Wx0 2:bx0 3:Wh0 4:bh0 5:Wx1 6:bx1 7:Wh1 8:bh1
    // 9:Wx2 10:bx2 11:Wh2 12:bh2 13:Wfc 14:bfc
    const float* x   = (const float*)d_in[0];
    const float* Wx0 = (const float*)d_in[1];
    const float* bx0 = (const float*)d_in[2];
    const float* bh0 = (const float*)d_in[4];
    const float* Wx1 = (const float*)d_in[5];
    const float* bx1 = (const float*)d_in[6];
    const float* bh1 = (const float*)d_in[8];
    const float* Wx2 = (const float*)d_in[9];
    const float* bx2 = (const float*)d_in[10];
    const float* bh2 = (const float*)d_in[12];
    const float* Wfc = (const float*)d_in[13];
    const float* bfc = (const float*)d_in[14];
    float* out = (float*)d_out;

    lstm_last_step_kernel<<<NBLOCKS, THREADS>>>(
        x, Wx0, bx0, bh0, Wx1, bx1, bh1, Wx2, bx2, bh2, Wfc, bfc, out);
}